// round 3
// baseline (speedup 1.0000x reference)
#include <cuda_runtime.h>
#include <cuda_bf16.h>
#include <math.h>

#define S_WORDS 2048
#define LMAX    16
#define CE      256
#define WE      512
#define HDIM    1024
#define GC      (4*CE)     // 1024 gate rows, char LSTM
#define GW      (4*HDIM)   // 4096 gate rows, word LSTM
#define KC      (2*CE)     // 512  (x | h) for char LSTM
#define KW      (WE+CE)    // 768  (we | char_feat)
#define NBLK_WL 128        // persistent blocks for word LSTM (<= 148 SMs)

// ---------------- device scratch (no allocations allowed) ----------------
__device__ float    g_WcT[KC*GC];        // [k=512][g=1024] transposed char weights
__device__ float    g_WihwT[KW*GW];      // [k=768][g=4096] transposed word input weights
__device__ float    g_lasth[S_WORDS*CE]; // char-LSTM output feature per word
__device__ float    g_GXw[S_WORDS*GW];   // precomputed x-part of word-LSTM gates (+bias)
__device__ float    g_hbuf[HDIM];        // word-LSTM h broadcast buffer
__device__ unsigned g_arrive;            // grid barrier counter

__device__ __forceinline__ float sigf(float x) { return 1.f / (1.f + __expf(-x)); }

// ---------------- prep: transpose weights, reset barrier ----------------
__global__ void prep_c(const float* __restrict__ Wih_c, const float* __restrict__ Whh_c) {
    int idx = blockIdx.x * blockDim.x + threadIdx.x;
    if (idx >= KC * GC) return;
    int k = idx / GC, g = idx % GC;
    g_WcT[idx] = (k < CE) ? Wih_c[g * CE + k] : Whh_c[g * CE + (k - CE)];
}

__global__ void prep_w(const float* __restrict__ Wih_w) {
    int idx = blockIdx.x * blockDim.x + threadIdx.x;
    if (idx == 0) g_arrive = 0u;
    if (idx >= KW * GW) return;
    int k = idx / GW, g = idx % GW;
    g_WihwT[idx] = Wih_w[g * KW + k];
}

// ---------------- char LSTM: 8 words per block, 16 timesteps ----------------
// SMEM: xh[8][512] (x|h per word), gates[8][1024]
__global__ void char_lstm(const int*   __restrict__ char_idxs,
                          const int*   __restrict__ char_lens,
                          const float* __restrict__ char_emb,
                          const float* __restrict__ bih_c,
                          const float* __restrict__ bhh_c)
{
    extern __shared__ float sm[];
    float* xh    = sm;            // 8*512
    float* gates = sm + 8 * KC;   // 8*1024
    const int tid   = threadIdx.x;      // 0..255
    const int wbase = blockIdx.x * 8;

    float bias[4];
#pragma unroll
    for (int q = 0; q < 4; q++) bias[q] = bih_c[4 * tid + q] + bhh_c[4 * tid + q];

    float c[8];
    int   len[8];
#pragma unroll
    for (int w = 0; w < 8; w++) {
        c[w]  = 0.f;
        len[w] = char_lens[wbase + w];
        xh[w * KC + CE + tid] = 0.f;   // h = 0
    }
    __syncthreads();

    const float4* Wp = reinterpret_cast<const float4*>(g_WcT) + tid;  // column block 4*tid

    for (int t = 0; t < LMAX; t++) {
        // gather x_t for the 8 words
#pragma unroll
        for (int w = 0; w < 8; w++) {
            int ci = char_idxs[(wbase + w) * LMAX + t];
            xh[w * KC + tid] = char_emb[ci * CE + tid];
        }
        __syncthreads();

        float acc[8][4];
#pragma unroll
        for (int w = 0; w < 8; w++)
#pragma unroll
            for (int q = 0; q < 4; q++) acc[w][q] = 0.f;

#pragma unroll 4
        for (int k = 0; k < KC; k++) {
            float4 wv = Wp[k * (GC / 4)];
#pragma unroll
            for (int w = 0; w < 8; w++) {
                float xv = xh[w * KC + k];
                acc[w][0] = fmaf(wv.x, xv, acc[w][0]);
                acc[w][1] = fmaf(wv.y, xv, acc[w][1]);
                acc[w][2] = fmaf(wv.z, xv, acc[w][2]);
                acc[w][3] = fmaf(wv.w, xv, acc[w][3]);
            }
        }
#pragma unroll
        for (int w = 0; w < 8; w++) {
            reinterpret_cast<float4*>(gates + w * GC)[tid] =
                make_float4(acc[w][0] + bias[0], acc[w][1] + bias[1],
                            acc[w][2] + bias[2], acc[w][3] + bias[3]);
        }
        __syncthreads();

        // cell update: thread tid owns hidden unit tid (torch gate order i,f,g,o)
#pragma unroll
        for (int w = 0; w < 8; w++) {
            float ig = gates[w * GC +            tid];
            float fg = gates[w * GC +     CE +   tid];
            float gg = gates[w * GC + 2 * CE +   tid];
            float og = gates[w * GC + 3 * CE +   tid];
            float cn = sigf(fg) * c[w] + sigf(ig) * tanhf(gg);
            float hn = sigf(og) * tanhf(cn);
            c[w] = cn;
            xh[w * KC + CE + tid] = hn;
            if (t == len[w] - 1) g_lasth[(wbase + w) * CE + tid] = hn;
        }
        __syncthreads();
    }
}

// ---------------- word-LSTM input GEMM: GXw = [we|last] @ Wih_w^T + bias ----------------
__global__ void word_gemm(const int*   __restrict__ word_idxs,
                          const float* __restrict__ word_emb,
                          const float* __restrict__ bih_w,
                          const float* __restrict__ bhh_w)
{
    extern __shared__ float xw[];   // [8][768]
    const int tid   = threadIdx.x;           // 0..255
    const int wbase = blockIdx.x * 8;
    const int gq    = blockIdx.y * 256 + tid; // float4 column index 0..1023

#pragma unroll
    for (int w = 0; w < 8; w++) {
        int wi = word_idxs[wbase + w];
        xw[w * KW +       tid] = word_emb[wi * WE +       tid];
        xw[w * KW + 256 + tid] = word_emb[wi * WE + 256 + tid];
        xw[w * KW + 512 + tid] = g_lasth[(wbase + w) * CE + tid];
    }
    __syncthreads();

    const int gbase = 4 * gq;
    float bias[4];
#pragma unroll
    for (int q = 0; q < 4; q++) bias[q] = bih_w[gbase + q] + bhh_w[gbase + q];

    float acc[8][4];
#pragma unroll
    for (int w = 0; w < 8; w++)
#pragma unroll
        for (int q = 0; q < 4; q++) acc[w][q] = 0.f;

    const float4* Wp = reinterpret_cast<const float4*>(g_WihwT) + gq;
#pragma unroll 4
    for (int k = 0; k < KW; k++) {
        float4 wv = Wp[k * (GW / 4)];
#pragma unroll
        for (int w = 0; w < 8; w++) {
            float xv = xw[w * KW + k];
            acc[w][0] = fmaf(wv.x, xv, acc[w][0]);
            acc[w][1] = fmaf(wv.y, xv, acc[w][1]);
            acc[w][2] = fmaf(wv.z, xv, acc[w][2]);
            acc[w][3] = fmaf(wv.w, xv, acc[w][3]);
        }
    }
#pragma unroll
    for (int w = 0; w < 8; w++) {
        reinterpret_cast<float4*>(g_GXw + (size_t)(wbase + w) * GW)[gq] =
            make_float4(acc[w][0] + bias[0], acc[w][1] + bias[1],
                        acc[w][2] + bias[2], acc[w][3] + bias[3]);
    }
}

// ---------------- word LSTM recurrence: persistent, register-resident Whh ----------------
// 128 blocks x 256 threads. Block b owns hidden units [8b, 8b+8).
// Warp y handles unit u = 8b + y; its 4 gate rows live in 128 registers/lane.
__global__ void __launch_bounds__(256, 1) word_lstm(const float* __restrict__ Whh_w,
                                                    float*       __restrict__ out)
{
    __shared__ float hs[HDIM];
    const int tid  = threadIdx.x;
    const int lane = tid & 31;
    const int y    = tid >> 5;
    const int u    = blockIdx.x * 8 + y;

    float w0[32], w1[32], w2[32], w3[32];
#pragma unroll
    for (int i = 0; i < 32; i++) {
        w0[i] = Whh_w[(0 * HDIM + u) * HDIM + i * 32 + lane];
        w1[i] = Whh_w[(1 * HDIM + u) * HDIM + i * 32 + lane];
        w2[i] = Whh_w[(2 * HDIM + u) * HDIM + i * 32 + lane];
        w3[i] = Whh_w[(3 * HDIM + u) * HDIM + i * 32 + lane];
    }
    for (int k = tid; k < HDIM; k += 256) hs[k] = 0.f;
    float c = 0.f;
    __syncthreads();

    for (int s = 0; s < S_WORDS; s++) {
        const float* gx = g_GXw + (size_t)s * GW;
        float gi0 = gx[u];
        float gf0 = gx[HDIM + u];
        float gg0 = gx[2 * HDIM + u];
        float go0 = gx[3 * HDIM + u];

        float a0 = 0.f, a1 = 0.f, a2 = 0.f, a3 = 0.f;
#pragma unroll
        for (int i = 0; i < 32; i++) {
            float hv = hs[i * 32 + lane];
            a0 = fmaf(w0[i], hv, a0);
            a1 = fmaf(w1[i], hv, a1);
            a2 = fmaf(w2[i], hv, a2);
            a3 = fmaf(w3[i], hv, a3);
        }
#pragma unroll
        for (int off = 16; off > 0; off >>= 1) {
            a0 += __shfl_xor_sync(0xffffffffu, a0, off);
            a1 += __shfl_xor_sync(0xffffffffu, a1, off);
            a2 += __shfl_xor_sync(0xffffffffu, a2, off);
            a3 += __shfl_xor_sync(0xffffffffu, a3, off);
        }

        float cn = sigf(gf0 + a1) * c + sigf(gi0 + a0) * tanhf(gg0 + a2);
        c = cn;
        float h = sigf(go0 + a3) * tanhf(cn);

        if (lane == 0) {
            out[(size_t)s * HDIM + u] = h;
            g_hbuf[u] = h;
            __threadfence();               // make h visible GPU-wide before arrive
        }
        __syncthreads();

        if (s == S_WORDS - 1) break;

        if (tid == 0) {
            atomicAdd(&g_arrive, 1u);
            const unsigned target = (unsigned)NBLK_WL * (unsigned)(s + 1);
            volatile unsigned* ga = &g_arrive;
            while (*ga < target) { }
            __threadfence();
        }
        __syncthreads();

        // reload broadcast h (bypass L1 for cross-SM coherence)
        for (int k = tid; k < HDIM; k += 256)
            hs[k] = ((volatile float*)g_hbuf)[k];
        __syncthreads();
    }
}

// ---------------- launch ----------------
extern "C" void kernel_launch(void* const* d_in, const int* in_sizes, int n_in,
                              void* d_out, int out_size)
{
    const int*   word_idxs = (const int*)  d_in[0];
    const int*   char_idxs = (const int*)  d_in[1];
    const int*   char_lens = (const int*)  d_in[2];
    const float* char_emb  = (const float*)d_in[3];
    const float* word_emb  = (const float*)d_in[4];
    const float* Wih_c     = (const float*)d_in[5];
    const float* Whh_c     = (const float*)d_in[6];
    const float* bih_c     = (const float*)d_in[7];
    const float* bhh_c     = (const float*)d_in[8];
    const float* Wih_w     = (const float*)d_in[9];
    const float* Whh_w     = (const float*)d_in[10];
    const float* bih_w     = (const float*)d_in[11];
    const float* bhh_w     = (const float*)d_in[12];
    float* out = (float*)d_out;

    const int char_smem = (8 * KC + 8 * GC) * (int)sizeof(float);   // 49152 B
    const int gemm_smem = 8 * KW * (int)sizeof(float);              // 24576 B
    cudaFuncSetAttribute(char_lstm, cudaFuncAttributeMaxDynamicSharedMemorySize, char_smem);
    cudaFuncSetAttribute(word_gemm, cudaFuncAttributeMaxDynamicSharedMemorySize, gemm_smem);

    prep_c<<<(KC * GC + 255) / 256, 256>>>(Wih_c, Whh_c);
    prep_w<<<(KW * GW + 255) / 256, 256>>>(Wih_w);   // also resets g_arrive

    char_lstm<<<S_WORDS / 8, 256, char_smem>>>(char_idxs, char_lens, char_emb, bih_c, bhh_c);

    word_gemm<<<dim3(S_WORDS / 8, 4), 256, gemm_smem>>>(word_idxs, word_emb, bih_w, bhh_w);

    word_lstm<<<NBLK_WL, 256>>>(Whh_w, out);
}